// round 2
// baseline (speedup 1.0000x reference)
#include <cuda_runtime.h>

#define NSTATE (1u << 22)

// XOR swizzle on float4-unit index: permutes within 128B rows only,
// preserves 16B alignment, spreads bank columns for strided patterns.
__device__ __forceinline__ int SW(int u) {
    return u ^ ((u >> 3) & 7) ^ ((u >> 6) & 7);
}

// one 2x2 rotation butterfly: new = (c*I - i*s*X) * old
__device__ __forceinline__ void gate1(float& r0, float& i0, float& r1, float& i1,
                                      float c, float s)
{
    float nr0 = c * r0 + s * i1;
    float ni0 = c * i0 - s * r1;
    float nr1 = c * r1 + s * i0;
    float ni1 = c * i1 - s * r0;
    r0 = nr0; i0 = ni0; r1 = nr1; i1 = ni1;
}

// gate applied to a pair of interleaved units (each = 2 complex: r0,i0,r1,i1)
__device__ __forceinline__ void gateU(float4& A, float4& B, float c, float s)
{
    gate1(A.x, A.y, B.x, B.y, c, s);
    gate1(A.z, A.w, B.z, B.w, c, s);
}

// ---------------------------------------------------------------------------
// Kernel A: gates on global bits 0..11 (angle[21..10]).
// Tile = 8192 contiguous complex. 256 threads x 32 complex (16 float4 units).
// Rounds: bits 0..4 (from global regs), 5..8, 9..11. All smem ops are 128-bit.
// ---------------------------------------------------------------------------
__global__ void __launch_bounds__(256) gateA(const float* __restrict__ xr,
                                             const float* __restrict__ xi,
                                             const float* __restrict__ ang,
                                             float* __restrict__ outr,
                                             float* __restrict__ outi)
{
    extern __shared__ float4 sm[];            // 4096 units = 64KB
    const int t = threadIdx.x;
    const unsigned base = (unsigned)blockIdx.x << 13;

    float C[12], S[12];
#pragma unroll
    for (int b = 0; b < 12; ++b)
        sincosf(0.5f * __ldg(ang + 21 - b), &S[b], &C[b]);   // bit b <-> angle[21-b]

    // ---- Round 1: 32 contiguous complex per thread, gates bits 0..4 ----
    float ar[32], ai[32];
    {
        const float4* pr = reinterpret_cast<const float4*>(xr + base) + t * 8;
        const float4* pi = reinterpret_cast<const float4*>(xi + base) + t * 8;
#pragma unroll
        for (int q = 0; q < 8; ++q) {
            float4 vr = pr[q], vi = pi[q];
            ar[4*q+0] = vr.x; ar[4*q+1] = vr.y; ar[4*q+2] = vr.z; ar[4*q+3] = vr.w;
            ai[4*q+0] = vi.x; ai[4*q+1] = vi.y; ai[4*q+2] = vi.z; ai[4*q+3] = vi.w;
        }
    }
#pragma unroll
    for (int b = 0; b < 5; ++b) {
        const int st = 1 << b;
#pragma unroll
        for (int p = 0; p < 32; ++p)
            if (!(p & st))
                gate1(ar[p], ai[p], ar[p|st], ai[p|st], C[b], S[b]);
    }
#pragma unroll
    for (int m = 0; m < 16; ++m)
        sm[SW(t * 16 + m)] = make_float4(ar[2*m], ai[2*m], ar[2*m+1], ai[2*m+1]);
    __syncthreads();

    float4 U[16];

    // ---- Round 2: gates bits 5..8 (unit bits 4..7) ----
    {
        const int lo = t & 15, hi = t >> 4;
#pragma unroll
        for (int j = 0; j < 16; ++j)
            U[j] = sm[SW(lo | (j << 4) | (hi << 8))];
#pragma unroll
        for (int b = 0; b < 4; ++b) {
            const int st = 1 << b;
#pragma unroll
            for (int p = 0; p < 16; ++p)
                if (!(p & st)) gateU(U[p], U[p|st], C[5+b], S[5+b]);
        }
#pragma unroll
        for (int j = 0; j < 16; ++j)
            sm[SW(lo | (j << 4) | (hi << 8))] = U[j];
    }
    __syncthreads();

    // ---- Round 3: gates bits 9..11, vectorized global store ----
    {
        const int pas = t & 127, b12 = t >> 7;   // pas = k bits 2..8, b12 = k bit 12
#pragma unroll
        for (int j = 0; j < 8; ++j)
#pragma unroll
            for (int v = 0; v < 2; ++v)          // v = k bit 1
                U[(j << 1) | v] = sm[SW(v | (pas << 1) | (j << 8) | (b12 << 11))];
        // gates: bit 9 -> reg stride 2, bit 10 -> 4, bit 11 -> 8
#pragma unroll
        for (int b = 0; b < 3; ++b) {
            const int st = 2 << b;
#pragma unroll
            for (int p = 0; p < 16; ++p)
                if (!(p & st)) gateU(U[p], U[p|st], C[9+b], S[9+b]);
        }
#pragma unroll
        for (int j = 0; j < 8; ++j) {
            unsigned k = base + ((unsigned)pas << 2) + ((unsigned)j << 9)
                              + ((unsigned)b12 << 12);
            float4 A = U[2*j], B = U[2*j+1];
            *reinterpret_cast<float4*>(outr + k) = make_float4(A.x, A.z, B.x, B.z);
            *reinterpret_cast<float4*>(outi + k) = make_float4(A.y, A.w, B.y, B.w);
        }
    }
}

// ---------------------------------------------------------------------------
// Kernel B: gates on global bits 12..21 (angle[9..0]). In-place on out.
// Tile = 8 contiguous (bits 0..2) x 1024 strided (h = bits 12..21).
// 256 threads x 32 complex (16 units). Rounds: h0..3, h4..7, h8..9.
// ---------------------------------------------------------------------------
__global__ void __launch_bounds__(256) gateB(float* __restrict__ dr,
                                             float* __restrict__ di,
                                             const float* __restrict__ ang)
{
    extern __shared__ float4 sm[];            // 4096 units = 64KB
    const int t = threadIdx.x;
    const unsigned base = (unsigned)blockIdx.x << 3;   // bits 3..11

    float C[10], S[10];
#pragma unroll
    for (int g = 0; g < 10; ++g)
        sincosf(0.5f * __ldg(ang + 9 - g), &S[g], &C[g]);   // bit 12+g <-> angle[9-g]

    // ---- fill: global -> shared, interleaving (r,i) into float4 units ----
#pragma unroll
    for (int q = 0; q < 4; ++q) {
        int h = q * 256 + t;
        unsigned g0 = ((unsigned)h << 12) + base;
        float4 r0 = *reinterpret_cast<const float4*>(dr + g0);
        float4 r1 = *reinterpret_cast<const float4*>(dr + g0 + 4);
        float4 i0 = *reinterpret_cast<const float4*>(di + g0);
        float4 i1 = *reinterpret_cast<const float4*>(di + g0 + 4);
        int ub = h << 2;
        sm[SW(ub + 0)] = make_float4(r0.x, i0.x, r0.y, i0.y);
        sm[SW(ub + 1)] = make_float4(r0.z, i0.z, r0.w, i0.w);
        sm[SW(ub + 2)] = make_float4(r1.x, i1.x, r1.y, i1.y);
        sm[SW(ub + 3)] = make_float4(r1.z, i1.z, r1.w, i1.w);
    }
    __syncthreads();

    float4 U[16];
    const int w = t & 3;                      // lo pair slot (lo = 2w, 2w+1)

    // ---- Round 1: gates h0..h3 ----
    {
        const int hp = t >> 2;                // h4..h9
#pragma unroll
        for (int j = 0; j < 16; ++j)
            U[j] = sm[SW((((hp << 4) | j) << 2) | w)];
#pragma unroll
        for (int b = 0; b < 4; ++b) {
            const int st = 1 << b;
#pragma unroll
            for (int p = 0; p < 16; ++p)
                if (!(p & st)) gateU(U[p], U[p|st], C[b], S[b]);
        }
#pragma unroll
        for (int j = 0; j < 16; ++j)
            sm[SW((((hp << 4) | j) << 2) | w)] = U[j];
    }
    __syncthreads();

    // ---- Round 2: gates h4..h7 ----
    {
        const int hl = (t >> 2) & 15, ht = t >> 6;   // hl = h0..h3, ht = h8..h9
#pragma unroll
        for (int j = 0; j < 16; ++j)
            U[j] = sm[SW((((ht << 8) | (j << 4) | hl) << 2) | w)];
#pragma unroll
        for (int b = 0; b < 4; ++b) {
            const int st = 1 << b;
#pragma unroll
            for (int p = 0; p < 16; ++p)
                if (!(p & st)) gateU(U[p], U[p|st], C[4+b], S[4+b]);
        }
#pragma unroll
        for (int j = 0; j < 16; ++j)
            sm[SW((((ht << 8) | (j << 4) | hl) << 2) | w)] = U[j];
    }
    __syncthreads();

    // ---- Round 3: gates h8,h9; registers ri = (h89<<2)|h01; global store ----
    {
        const int hmid = t >> 2;              // h2..h7
#pragma unroll
        for (int h89 = 0; h89 < 4; ++h89)
#pragma unroll
            for (int h01 = 0; h01 < 4; ++h01)
                U[(h89 << 2) | h01] =
                    sm[SW((((h89 << 8) | (hmid << 2) | h01) << 2) | w)];
        // h8 -> reg stride 4 (C[8]), h9 -> stride 8 (C[9])
#pragma unroll
        for (int b = 0; b < 2; ++b) {
            const int st = 4 << b;
#pragma unroll
            for (int p = 0; p < 16; ++p)
                if (!(p & st)) gateU(U[p], U[p|st], C[8+b], S[8+b]);
        }
#pragma unroll
        for (int ri = 0; ri < 16; ++ri) {
            int h = ((ri >> 2) << 8) | (hmid << 2) | (ri & 3);
            unsigned g0 = ((unsigned)h << 12) + base + 2u * (unsigned)w;
            float4 A = U[ri];
            *reinterpret_cast<float2*>(dr + g0) = make_float2(A.x, A.z);
            *reinterpret_cast<float2*>(di + g0) = make_float2(A.y, A.w);
        }
    }
}

extern "C" void kernel_launch(void* const* d_in, const int* in_sizes, int n_in,
                              void* d_out, int out_size)
{
    const float* xr  = (const float*)d_in[0];
    const float* xi  = (const float*)d_in[1];
    const float* ang = (const float*)d_in[2];
    float* outr = (float*)d_out;
    float* outi = outr + NSTATE;

    const int shmem = 4096 * sizeof(float4);  // 64KB
    cudaFuncSetAttribute(gateA, cudaFuncAttributeMaxDynamicSharedMemorySize, shmem);
    cudaFuncSetAttribute(gateB, cudaFuncAttributeMaxDynamicSharedMemorySize, shmem);

    // Pass 1: gates on bits 0..11 (input -> out)
    gateA<<<NSTATE / 8192, 256, shmem>>>(xr, xi, ang, outr, outi);

    // Pass 2: gates on bits 12..21 (in-place on out)
    gateB<<<NSTATE / 8192, 256, shmem>>>(outr, outi, ang);
}